// round 14
// baseline (speedup 1.0000x reference)
#include <cuda_runtime.h>
#include <cuda_bf16.h>
#include <math.h>
#include <float.h>
#include <stdint.h>

#define SEQ     4096
#define DMODEL  1024
#define NHEADS  16
#define HSIZE   64
#define QKVDIM  3072

// ---------------------------------------------------------------------------
// Scratch (__device__ globals; allocation-free rule)
// ---------------------------------------------------------------------------
__device__ __nv_bfloat16 g_xhi  [(size_t)SEQ * DMODEL];
__device__ __nv_bfloat16 g_xlo  [(size_t)SEQ * DMODEL];
__device__ __nv_bfloat16 g_w1hi [(size_t)QKVDIM * DMODEL];
__device__ __nv_bfloat16 g_w1lo [(size_t)QKVDIM * DMODEL];
__device__ __nv_bfloat16 g_w2hi [(size_t)DMODEL * DMODEL];
__device__ __nv_bfloat16 g_w2lo [(size_t)DMODEL * DMODEL];
__device__ __nv_bfloat16 g_qkvhi[(size_t)SEQ * QKVDIM];   // q(pre-scaled)|k|v, RoPE'd, split
__device__ __nv_bfloat16 g_qkvlo[(size_t)SEQ * QKVDIM];
__device__ __nv_bfloat16 g_ahi  [(size_t)SEQ * DMODEL];   // attention out, split
__device__ __nv_bfloat16 g_alo  [(size_t)SEQ * DMODEL];
__device__ float g_cos[(size_t)SEQ * 32];
__device__ float g_sin[(size_t)SEQ * 32];

// q prescale: 1/sqrt(64) * log2(e)  (exp2-domain softmax)
#define QSCALE (0.125f * 1.4426950408889634f)

// ---------------------------------------------------------------------------
// Helpers (base-ISA: mma.sync / ldmatrix / cp.async)
// ---------------------------------------------------------------------------
__device__ __forceinline__ uint32_t smem_u32(const void* p) {
    uint32_t a;
    asm("{ .reg .u64 t; cvta.to.shared.u64 t, %1; cvt.u32.u64 %0, t; }" : "=r"(a) : "l"(p));
    return a;
}
__device__ __forceinline__ float ex2(float x) {       // guaranteed single-MUFU path
    float y;
    asm("ex2.approx.f32 %0, %1;" : "=f"(y) : "f"(x));
    return y;
}
__device__ __forceinline__ void mma_bf16(float d[4], const uint32_t a[4],
                                         uint32_t b0, uint32_t b1) {
    asm volatile("mma.sync.aligned.m16n8k16.row.col.f32.bf16.bf16.f32 "
        "{%0,%1,%2,%3}, {%4,%5,%6,%7}, {%8,%9}, {%0,%1,%2,%3};"
        : "+f"(d[0]), "+f"(d[1]), "+f"(d[2]), "+f"(d[3])
        : "r"(a[0]), "r"(a[1]), "r"(a[2]), "r"(a[3]), "r"(b0), "r"(b1));
}
__device__ __forceinline__ void ldsm_x4(uint32_t r[4], uint32_t addr) {
    asm volatile("ldmatrix.sync.aligned.m8n8.x4.shared.b16 {%0,%1,%2,%3}, [%4];"
        : "=r"(r[0]), "=r"(r[1]), "=r"(r[2]), "=r"(r[3]) : "r"(addr));
}
__device__ __forceinline__ void ldsm_x4_t(uint32_t r[4], uint32_t addr) {
    asm volatile("ldmatrix.sync.aligned.m8n8.x4.trans.shared.b16 {%0,%1,%2,%3}, [%4];"
        : "=r"(r[0]), "=r"(r[1]), "=r"(r[2]), "=r"(r[3]) : "r"(addr));
}
// Split (x,y) fp32 -> packed bf16x2 hi/lo. Bit-identical to scalar rn split.
__device__ __forceinline__ void split2(float x, float y, uint32_t& h, uint32_t& l) {
    uint32_t H, L;
    asm("cvt.rn.bf16x2.f32 %0, %1, %2;" : "=r"(H) : "f"(y), "f"(x));   // hi16=y, lo16=x
    float hx = __uint_as_float(H << 16);
    float hy = __uint_as_float(H & 0xffff0000u);
    float lx = x - hx, ly = y - hy;
    asm("cvt.rn.bf16x2.f32 %0, %1, %2;" : "=r"(L) : "f"(ly), "f"(lx));
    h = H; l = L;
}
#define CP16(dst, src) asm volatile("cp.async.cg.shared.global [%0], [%1], 16;" \
                                    :: "r"(dst), "l"(src))
#define CP_COMMIT() asm volatile("cp.async.commit_group;" ::: "memory")
#define CP_WAIT1()  asm volatile("cp.async.wait_group 1;" ::: "memory")
#define CP_WAIT0()  asm volatile("cp.async.wait_group 0;" ::: "memory")

// 128B rows (64 bf16): chunk c in 0..7
__device__ __forceinline__ uint32_t swz128(int row, int c) {
    return (uint32_t)(row * 128 + ((c ^ (row & 7)) << 4));
}
// 64B rows (32 bf16): chunk c in 0..3
__device__ __forceinline__ uint32_t swz64(int row, int c) {
    return (uint32_t)(row * 64 + ((c ^ ((row & 7) >> 1)) << 4));
}

// ---------------------------------------------------------------------------
// Fused prep kernel: x-split | W1-split | RoPE tables, branched on blockIdx.
// ---------------------------------------------------------------------------
#define XSPLIT_BLKS   (SEQ * DMODEL / 4 / 256)            // 1024
#define W1SPLIT_BLKS  (QKVDIM * DMODEL / 4 / 256)         // 3072
#define ROPE_BLKS     (SEQ * 32 / 256)                    // 512
#define PREP_BLKS     (XSPLIT_BLKS + W1SPLIT_BLKS + ROPE_BLKS)

__device__ __forceinline__ void split_chunk(const float* __restrict__ in,
                                            __nv_bfloat16* __restrict__ hi,
                                            __nv_bfloat16* __restrict__ lo, int i)
{
    float4 v = ((const float4*)in)[i];
    uint32_t h0, l0, h1, l1;
    split2(v.x, v.y, h0, l0);
    split2(v.z, v.w, h1, l1);
    ((uint32_t*)hi)[2 * i]     = h0;
    ((uint32_t*)hi)[2 * i + 1] = h1;
    ((uint32_t*)lo)[2 * i]     = l0;
    ((uint32_t*)lo)[2 * i + 1] = l1;
}

__global__ void k_prep(const float* __restrict__ x, const float* __restrict__ W1,
                       const int* __restrict__ pos)
{
    int b = blockIdx.x;
    if (b < XSPLIT_BLKS) {
        split_chunk(x, g_xhi, g_xlo, b * 256 + threadIdx.x);
    } else if (b < XSPLIT_BLKS + W1SPLIT_BLKS) {
        split_chunk(W1, g_w1hi, g_w1lo, (b - XSPLIT_BLKS) * 256 + threadIdx.x);
    } else {
        int i = (b - XSPLIT_BLKS - W1SPLIT_BLKS) * 256 + threadIdx.x;
        int m = i >> 5, k = i & 31;
        float invf = 1.0f / powf(10000.0f, (2.0f * (float)k) / 64.0f);
        float ang = (float)pos[m] * invf;
        float sn, cs;
        sincosf(ang, &sn, &cs);
        g_cos[i] = cs; g_sin[i] = sn;
    }
}

__global__ void k_split(const float* __restrict__ in, __nv_bfloat16* __restrict__ hi,
                        __nv_bfloat16* __restrict__ lo, int n4)
{
    int i = blockIdx.x * blockDim.x + threadIdx.x;
    if (i >= n4) return;
    split_chunk(in, hi, lo, i);
}

// ---------------------------------------------------------------------------
// Projection GEMM: C[M,N] = A[M,K] @ B[N,K]^T, bf16 3-product split.
// CTA 128x128, BK=32, 3-stage cp.async, single sync/iter, 2 CTAs/SM. (R8)
// ---------------------------------------------------------------------------
#define GARR   8192                         // 128 rows x 64B
#define GSTAGE (4 * GARR)                   // 32KB
#define GEMM_SMEM (3 * GSTAGE)              // 98304 B

template<int EPI>
__global__ __launch_bounds__(256, 2)
void mma_gemm(const __nv_bfloat16* __restrict__ Ahi, const __nv_bfloat16* __restrict__ Alo,
              const __nv_bfloat16* __restrict__ Bhi, const __nv_bfloat16* __restrict__ Blo,
              float* __restrict__ Cf, __nv_bfloat16* __restrict__ Chi,
              __nv_bfloat16* __restrict__ Clo, int M, int N, int K)
{
    extern __shared__ __nv_bfloat16 dsm[];
    const uint32_t sb = smem_u32(dsm);
    const int tid = threadIdx.x, lane = tid & 31, wid = tid >> 5;
    const int m0 = blockIdx.y * 128, n0 = blockIdx.x * 128;
    const int wm = (wid & 1) * 64, wn = (wid >> 1) * 32;

    const int arow = lane & 15,                    acol = (lane & 16) ? 1 : 0;
    const int brow = (lane & 7) + ((lane & 16) ? 8 : 0), bcol = (lane & 8) ? 1 : 0;

    float acc[4][4][4];
#pragma unroll
    for (int a = 0; a < 4; a++)
#pragma unroll
        for (int b = 0; b < 4; b++)
#pragma unroll
            for (int c = 0; c < 4; c++) acc[a][b][c] = 0.f;

    const int nk = K >> 5;

    auto load_stage = [&](int kc, int s) {
        const uint32_t base = sb + (uint32_t)s * GSTAGE;
#pragma unroll
        for (int u = 0; u < 2; u++) {
            int id = tid + u * 256;
            int r = id >> 2, c = id & 3;
            uint32_t so = swz64(r, c);
            size_t ga = (size_t)(m0 + r) * K + kc + c * 8;
            size_t gb = (size_t)(n0 + r) * K + kc + c * 8;
            CP16(base +            so, Ahi + ga);
            CP16(base +     GARR + so, Alo + ga);
            CP16(base + 2 * GARR + so, Bhi + gb);
            CP16(base + 3 * GARR + so, Blo + gb);
        }
        CP_COMMIT();
    };

    load_stage(0, 0);
    load_stage(32, 1);

    for (int kc = 0; kc < nk; kc++) {
        const int cur = kc % 3;
        if (kc == nk - 1) { CP_WAIT0(); } else { CP_WAIT1(); }
        __syncthreads();
        if (kc + 2 < nk) load_stage((kc + 2) << 5, (kc + 2) % 3);

        const uint32_t ab = sb + (uint32_t)cur * GSTAGE;
        const uint32_t bb = ab + 2 * GARR;
#pragma unroll
        for (int ks = 0; ks < 2; ks++) {
            uint32_t ah[4][4], al[4][4];
#pragma unroll
            for (int mf = 0; mf < 4; mf++) {
                uint32_t off = swz64(wm + mf * 16 + arow, ks * 2 + acol);
                ldsm_x4(ah[mf], ab + off);
                ldsm_x4(al[mf], ab + GARR + off);
            }
#pragma unroll
            for (int np = 0; np < 2; np++) {
                uint32_t bh[4], bl[4];
                uint32_t off = swz64(wn + np * 16 + brow, ks * 2 + bcol);
                ldsm_x4(bh, bb + off);
                ldsm_x4(bl, bb + GARR + off);
#pragma unroll
                for (int sel = 0; sel < 2; sel++) {
                    const int nf = np * 2 + sel;
                    uint32_t bh0 = bh[sel * 2], bh1 = bh[sel * 2 + 1];
                    uint32_t bl0 = bl[sel * 2], bl1 = bl[sel * 2 + 1];
#pragma unroll
                    for (int mf = 0; mf < 4; mf++) {
                        mma_bf16(acc[mf][nf], ah[mf], bh0, bh1);
                        mma_bf16(acc[mf][nf], ah[mf], bl0, bl1);
                        mma_bf16(acc[mf][nf], al[mf], bh0, bh1);
                    }
                }
            }
        }
    }

    // epilogue
#pragma unroll
    for (int mf = 0; mf < 4; mf++) {
#pragma unroll
        for (int hf = 0; hf < 2; hf++) {
            const int row = m0 + wm + mf * 16 + (lane >> 2) + hf * 8;
#pragma unroll
            for (int nf = 0; nf < 4; nf++) {
                const int col = n0 + wn + nf * 8 + (lane & 3) * 2;
                float v0 = acc[mf][nf][hf * 2], v1 = acc[mf][nf][hf * 2 + 1];
                if (EPI == 1) {
                    if (col < 2 * DMODEL) {
                        int kidx = (col & 63) >> 1;
                        float cs = g_cos[row * 32 + kidx];
                        float sn = g_sin[row * 32 + kidx];
                        float e = v0, o = v1;
                        v0 = e * cs - o * sn;
                        v1 = o * cs + e * sn;
                        if (col < DMODEL) { v0 *= QSCALE; v1 *= QSCALE; }
                    }
                    uint32_t h, l;
                    split2(v0, v1, h, l);
                    *(uint32_t*)(Chi + (size_t)row * N + col) = h;
                    *(uint32_t*)(Clo + (size_t)row * N + col) = l;
                } else {
                    *(float2*)(Cf + (size_t)row * N + col) = make_float2(v0, v1);
                }
            }
        }
    }
}

// ---------------------------------------------------------------------------
// Causal flash attention: Q-tile 192, 12 warps (384 thr) -> 3 warps/SMSP,
// K-tile 128 (two 64-col passes), single-sync double buffer, no-max exp2
// softmax with DEFERRED lr reduction (shfl only in epilogue).
// ---------------------------------------------------------------------------
#define QROWS     192
#define ATT_THR   384
#define ATT_QARR  (QROWS * 128)              // 24576 B
#define ATT_KARR  16384                      // 128 rows x 128B
#define ATT_SMEM  (2 * ATT_QARR + 2 * 4 * ATT_KARR)   // 180224 B
#define ATT_GRID  ((SEQ + QROWS - 1) / QROWS)          // 22

__global__ __launch_bounds__(ATT_THR)
void attn_mma()
{
    extern __shared__ __nv_bfloat16 sm[];
    const uint32_t sb  = smem_u32(sm);
    const uint32_t kvb = sb + 2 * ATT_QARR;

    const int h   = blockIdx.y;
    const int qt  = gridDim.x - 1 - blockIdx.x;    // big tiles first
    const int tid = threadIdx.x;
    const int lane = tid & 31, w = tid >> 5;       // w in 0..11

    const int arow = lane & 15,                    acol = (lane & 16) ? 1 : 0;
    const int brow = (lane & 7) + ((lane & 16) ? 8 : 0), bcol = (lane & 8) ? 1 : 0;

    // async Q load (joins K/V stage-0 commit group); clamp OOB rows to SEQ-1
#pragma unroll
    for (int u = 0; u < 4; u++) {
        int id = tid + u * ATT_THR;                // 0..1535
        int r = id >> 3, c = id & 7;
        int gr = qt * QROWS + r;
        if (gr > SEQ - 1) gr = SEQ - 1;
        uint32_t so = swz128(r, c);
        size_t g = (size_t)gr * QKVDIM + h * HSIZE + c * 8;
        CP16(sb + so,            g_qkvhi + g);
        CP16(sb + ATT_QARR + so, g_qkvlo + g);
    }

    auto load_kv = [&](int kt, int s) {
        const size_t kb = (size_t)(kt * 128) * QKVDIM + DMODEL + h * HSIZE;
        const size_t vb = kb + DMODEL;
        const uint32_t base = kvb + (uint32_t)(s * 4) * ATT_KARR;
#pragma unroll
        for (int u = 0; u < 3; u++) {
            int id = tid + u * ATT_THR;
            if (id < 1024) {
                int r = id >> 3, c = id & 7;
                uint32_t so = swz128(r, c);
                size_t gk = kb + (size_t)r * QKVDIM + c * 8;
                size_t gv = vb + (size_t)r * QKVDIM + c * 8;
                CP16(base +                so, g_qkvhi + gk);
                CP16(base +     ATT_KARR + so, g_qkvlo + gk);
                CP16(base + 2 * ATT_KARR + so, g_qkvhi + gv);
                CP16(base + 3 * ATT_KARR + so, g_qkvlo + gv);
            }
        }
        CP_COMMIT();
    };

    load_kv(0, 0);

    uint32_t qfh[4][4], qfl[4][4];
    float o[8][4];
#pragma unroll
    for (int i = 0; i < 8; i++)
#pragma unroll
        for (int j = 0; j < 4; j++) o[i][j] = 0.f;
    float lr[2] = { 0.f, 0.f };

    const int wrow  = qt * QROWS + w * 16;     // warp's first global q row (may exceed SEQ)
    int ktmax = (qt * QROWS + QROWS - 1) >> 7;
    if (ktmax > SEQ / 128 - 1) ktmax = SEQ / 128 - 1;

    for (int kt = 0; kt <= ktmax; kt++) {
        const int cur = kt & 1;
        CP_WAIT0();
        __syncthreads();
        if (kt < ktmax) load_kv(kt + 1, cur ^ 1);

        if (kt == 0) {
#pragma unroll
            for (int t = 0; t < 4; t++) {
                uint32_t off = swz128(w * 16 + arow, t * 2 + acol);
                ldsm_x4(qfh[t], sb + off);
                ldsm_x4(qfl[t], sb + ATT_QARR + off);
            }
        }

        const uint32_t kbh = kvb + (uint32_t)(cur * 4) * ATT_KARR;
        const uint32_t kbl = kbh + ATT_KARR;
        const uint32_t vbh = kbh + 2 * ATT_KARR;
        const uint32_t vbl = kbh + 3 * ATT_KARR;

#pragma unroll
        for (int half = 0; half < 2; half++) {
            const int colbase = kt * 128 + half * 64;
            if (colbase > wrow + 15) continue;       // fully masked for this warp
            const int rbase = half * 64;             // k-row offset inside the tile

            float s[8][4];
#pragma unroll
            for (int i = 0; i < 8; i++)
#pragma unroll
                for (int j = 0; j < 4; j++) s[i][j] = 0.f;

            // S = Q' K^T (scale+log2e pre-folded into Q)
#pragma unroll
            for (int t = 0; t < 4; t++) {
#pragma unroll
                for (int np = 0; np < 4; np++) {
                    uint32_t bh[4], bl[4];
                    uint32_t off = swz128(rbase + np * 16 + brow, t * 2 + bcol);
                    ldsm_x4(bh, kbh + off);
                    ldsm_x4(bl, kbl + off);
#pragma unroll
                    for (int sel = 0; sel < 2; sel++) {
                        const int nf = np * 2 + sel;
                        uint32_t b0h = bh[sel * 2], b1h = bh[sel * 2 + 1];
                        uint32_t b0l = bl[sel * 2], b1l = bl[sel * 2 + 1];
                        mma_bf16(s[nf], qfh[t], b0h, b1h);
                        mma_bf16(s[nf], qfh[t], b0l, b1l);
                        mma_bf16(s[nf], qfl[t], b0h, b1h);
                    }
                }
            }

            // causal mask (only if this half crosses the warp's rows)
            if (colbase + 63 > wrow) {
                const int r0 = wrow + (lane >> 2), r1 = r0 + 8;
                const int cb = colbase + (lane & 3) * 2;
#pragma unroll
                for (int nf = 0; nf < 8; nf++) {
                    const int c0 = cb + nf * 8;
                    if (c0     > r0) s[nf][0] = -FLT_MAX;
                    if (c0 + 1 > r0) s[nf][1] = -FLT_MAX;
                    if (c0     > r1) s[nf][2] = -FLT_MAX;
                    if (c0 + 1 > r1) s[nf][3] = -FLT_MAX;
                }
            }

            // NO-MAX softmax (exp2 domain, MUFU ex2): p = 2^s; deferred lr.
#pragma unroll
            for (int hf = 0; hf < 2; hf++) {
                float rs = 0.f;
#pragma unroll
                for (int nf = 0; nf < 8; nf++) {
                    float p0 = ex2(s[nf][hf * 2]);
                    float p1 = ex2(s[nf][hf * 2 + 1]);
                    s[nf][hf * 2]     = p0;
                    s[nf][hf * 2 + 1] = p1;
                    rs += p0 + p1;
                }
                lr[hf] += rs;                      // per-thread partial; reduce at end
            }

            // O += P V (P re-split in-register; V via ldmatrix.trans)
#pragma unroll
            for (int t = 0; t < 4; t++) {
                uint32_t ph[4], pl[4];
                split2(s[2 * t][0],     s[2 * t][1],     ph[0], pl[0]);
                split2(s[2 * t][2],     s[2 * t][3],     ph[1], pl[1]);
                split2(s[2 * t + 1][0], s[2 * t + 1][1], ph[2], pl[2]);
                split2(s[2 * t + 1][2], s[2 * t + 1][3], ph[3], pl[3]);
#pragma unroll
                for (int np = 0; np < 4; np++) {
                    uint32_t vh4[4], vl4[4];
                    uint32_t off = swz128(rbase + t * 16 + arow, np * 2 + acol);
                    ldsm_x4_t(vh4, vbh + off);
                    ldsm_x4_t(vl4, vbl + off);
#pragma unroll
                    for (int sel = 0; sel < 2; sel++) {
                        const int df = np * 2 + sel;
                        uint32_t v0h = vh4[sel * 2], v1h = vh4[sel * 2 + 1];
                        uint32_t v0l = vl4[sel * 2], v1l = vl4[sel * 2 + 1];
                        mma_bf16(o[df], ph, v0h, v1h);
                        mma_bf16(o[df], ph, v0l, v1l);
                        mma_bf16(o[df], pl, v0h, v1h);
                    }
                }
            }
        }
    }

    // epilogue: final lr reduction, normalize, split, store
#pragma unroll
    for (int hf = 0; hf < 2; hf++) {
        float t = lr[hf];
        t += __shfl_xor_sync(0xffffffffu, t, 1);
        t += __shfl_xor_sync(0xffffffffu, t, 2);
        lr[hf] = t;
    }
#pragma unroll
    for (int hf = 0; hf < 2; hf++) {
        const float inv = 1.0f / lr[hf];
        const int row = wrow + (lane >> 2) + hf * 8;
        if (row < SEQ) {
#pragma unroll
            for (int df = 0; df < 8; df++) {
                const int col = h * 64 + df * 8 + (lane & 3) * 2;
                float v0 = o[df][hf * 2] * inv, v1 = o[df][hf * 2 + 1] * inv;
                uint32_t hh, ll;
                split2(v0, v1, hh, ll);
                *(uint32_t*)(g_ahi + (size_t)row * DMODEL + col) = hh;
                *(uint32_t*)(g_alo + (size_t)row * DMODEL + col) = ll;
            }
        }
    }
}

// ---------------------------------------------------------------------------
extern "C" void kernel_launch(void* const* d_in, const int* in_sizes, int n_in,
                              void* d_out, int out_size)
{
    const float* x    = (const float*)d_in[0];
    const int*   pos  = (const int*)  d_in[1];
    const float* Wqkv = (const float*)d_in[2];
    const float* Wo   = (const float*)d_in[3];
    float*       out  = (float*)d_out;

    __nv_bfloat16 *xhi, *xlo, *w1hi, *w1lo, *w2hi, *w2lo, *qkvhi, *qkvlo, *ahi, *alo;
    cudaGetSymbolAddress((void**)&xhi,   g_xhi);
    cudaGetSymbolAddress((void**)&xlo,   g_xlo);
    cudaGetSymbolAddress((void**)&w1hi,  g_w1hi);
    cudaGetSymbolAddress((void**)&w1lo,  g_w1lo);
    cudaGetSymbolAddress((void**)&w2hi,  g_w2hi);
    cudaGetSymbolAddress((void**)&w2lo,  g_w2lo);
    cudaGetSymbolAddress((void**)&qkvhi, g_qkvhi);
    cudaGetSymbolAddress((void**)&qkvlo, g_qkvlo);
    cudaGetSymbolAddress((void**)&ahi,   g_ahi);
    cudaGetSymbolAddress((void**)&alo,   g_alo);

    cudaFuncSetAttribute(mma_gemm<1>,
                         cudaFuncAttributeMaxDynamicSharedMemorySize, GEMM_SMEM);
    cudaFuncSetAttribute(mma_gemm<0>,
                         cudaFuncAttributeMaxDynamicSharedMemorySize, GEMM_SMEM);
    cudaFuncSetAttribute(attn_mma,
                         cudaFuncAttributeMaxDynamicSharedMemorySize, ATT_SMEM);

    // 1) fused prep: x-split + W1-split + RoPE tables
    k_prep<<<PREP_BLKS, 256>>>(x, Wqkv, pos);

    // 2) QKV projection + RoPE + q-prescale + split store
    mma_gemm<1><<<dim3(QKVDIM / 128, SEQ / 128), 256, GEMM_SMEM>>>(
        xhi, xlo, w1hi, w1lo, nullptr, qkvhi, qkvlo, SEQ, QKVDIM, DMODEL);

    // 3) W_o split (independent)
    k_split<<<(DMODEL * DMODEL / 4 + 255) / 256, 256>>>(Wo, w2hi, w2lo, DMODEL * DMODEL / 4);

    // 4) Causal flash attention (Q-tile 192, 12 warps)  <-- ncu capture here
    attn_mma<<<dim3(ATT_GRID, NHEADS), ATT_THR, ATT_SMEM>>>();

    // 5) Output projection -> fp32 out
    mma_gemm<0><<<dim3(DMODEL / 128, SEQ / 128), 256, GEMM_SMEM>>>(
        ahi, alo, w2hi, w2lo, out, nullptr, nullptr, SEQ, DMODEL, DMODEL);
}

// round 15
// speedup vs baseline: 1.0925x; 1.0925x over previous
#include <cuda_runtime.h>
#include <cuda_bf16.h>
#include <math.h>
#include <float.h>
#include <stdint.h>

#define SEQ     4096
#define DMODEL  1024
#define NHEADS  16
#define HSIZE   64
#define QKVDIM  3072

// ---------------------------------------------------------------------------
// Scratch (__device__ globals; allocation-free rule)
// ---------------------------------------------------------------------------
__device__ __nv_bfloat16 g_xhi  [(size_t)SEQ * DMODEL];
__device__ __nv_bfloat16 g_xlo  [(size_t)SEQ * DMODEL];
__device__ __nv_bfloat16 g_w1hi [(size_t)QKVDIM * DMODEL];
__device__ __nv_bfloat16 g_w1lo [(size_t)QKVDIM * DMODEL];
__device__ __nv_bfloat16 g_w2hi [(size_t)DMODEL * DMODEL];
__device__ __nv_bfloat16 g_w2lo [(size_t)DMODEL * DMODEL];
__device__ __nv_bfloat16 g_qkvhi[(size_t)SEQ * QKVDIM];   // q(pre-scaled)|k|v, RoPE'd, split
__device__ __nv_bfloat16 g_qkvlo[(size_t)SEQ * QKVDIM];
__device__ __nv_bfloat16 g_ahi  [(size_t)SEQ * DMODEL];   // attention out, split
__device__ __nv_bfloat16 g_alo  [(size_t)SEQ * DMODEL];
__device__ float g_cos[(size_t)SEQ * 32];
__device__ float g_sin[(size_t)SEQ * 32];

// q prescale: 1/sqrt(64) * log2(e)  (exp2-domain softmax)
#define QSCALE (0.125f * 1.4426950408889634f)

// ---------------------------------------------------------------------------
// Helpers (base-ISA: mma.sync / ldmatrix / cp.async)
// ---------------------------------------------------------------------------
__device__ __forceinline__ uint32_t smem_u32(const void* p) {
    uint32_t a;
    asm("{ .reg .u64 t; cvta.to.shared.u64 t, %1; cvt.u32.u64 %0, t; }" : "=r"(a) : "l"(p));
    return a;
}
__device__ __forceinline__ float ex2(float x) {       // guaranteed single-MUFU path
    float y;
    asm("ex2.approx.f32 %0, %1;" : "=f"(y) : "f"(x));
    return y;
}
__device__ __forceinline__ void mma_bf16(float d[4], const uint32_t a[4],
                                         uint32_t b0, uint32_t b1) {
    asm volatile("mma.sync.aligned.m16n8k16.row.col.f32.bf16.bf16.f32 "
        "{%0,%1,%2,%3}, {%4,%5,%6,%7}, {%8,%9}, {%0,%1,%2,%3};"
        : "+f"(d[0]), "+f"(d[1]), "+f"(d[2]), "+f"(d[3])
        : "r"(a[0]), "r"(a[1]), "r"(a[2]), "r"(a[3]), "r"(b0), "r"(b1));
}
__device__ __forceinline__ void ldsm_x4(uint32_t r[4], uint32_t addr) {
    asm volatile("ldmatrix.sync.aligned.m8n8.x4.shared.b16 {%0,%1,%2,%3}, [%4];"
        : "=r"(r[0]), "=r"(r[1]), "=r"(r[2]), "=r"(r[3]) : "r"(addr));
}
__device__ __forceinline__ void ldsm_x4_t(uint32_t r[4], uint32_t addr) {
    asm volatile("ldmatrix.sync.aligned.m8n8.x4.trans.shared.b16 {%0,%1,%2,%3}, [%4];"
        : "=r"(r[0]), "=r"(r[1]), "=r"(r[2]), "=r"(r[3]) : "r"(addr));
}
// Split (x,y) fp32 -> packed bf16x2 hi/lo. Bit-identical to scalar rn split.
__device__ __forceinline__ void split2(float x, float y, uint32_t& h, uint32_t& l) {
    uint32_t H, L;
    asm("cvt.rn.bf16x2.f32 %0, %1, %2;" : "=r"(H) : "f"(y), "f"(x));   // hi16=y, lo16=x
    float hx = __uint_as_float(H << 16);
    float hy = __uint_as_float(H & 0xffff0000u);
    float lx = x - hx, ly = y - hy;
    asm("cvt.rn.bf16x2.f32 %0, %1, %2;" : "=r"(L) : "f"(ly), "f"(lx));
    h = H; l = L;
}
#define CP16(dst, src) asm volatile("cp.async.cg.shared.global [%0], [%1], 16;" \
                                    :: "r"(dst), "l"(src))
#define CP_COMMIT() asm volatile("cp.async.commit_group;" ::: "memory")
#define CP_WAIT1()  asm volatile("cp.async.wait_group 1;" ::: "memory")
#define CP_WAIT0()  asm volatile("cp.async.wait_group 0;" ::: "memory")

// 128B rows (64 bf16): chunk c in 0..7
__device__ __forceinline__ uint32_t swz128(int row, int c) {
    return (uint32_t)(row * 128 + ((c ^ (row & 7)) << 4));
}
// 64B rows (32 bf16): chunk c in 0..3
__device__ __forceinline__ uint32_t swz64(int row, int c) {
    return (uint32_t)(row * 64 + ((c ^ ((row & 7) >> 1)) << 4));
}

// ---------------------------------------------------------------------------
// Fused prep kernel: x-split | W1-split | RoPE tables, branched on blockIdx.
// ---------------------------------------------------------------------------
#define XSPLIT_BLKS   (SEQ * DMODEL / 4 / 256)            // 1024
#define W1SPLIT_BLKS  (QKVDIM * DMODEL / 4 / 256)         // 3072
#define ROPE_BLKS     (SEQ * 32 / 256)                    // 512
#define PREP_BLKS     (XSPLIT_BLKS + W1SPLIT_BLKS + ROPE_BLKS)

__device__ __forceinline__ void split_chunk(const float* __restrict__ in,
                                            __nv_bfloat16* __restrict__ hi,
                                            __nv_bfloat16* __restrict__ lo, int i)
{
    float4 v = ((const float4*)in)[i];
    uint32_t h0, l0, h1, l1;
    split2(v.x, v.y, h0, l0);
    split2(v.z, v.w, h1, l1);
    ((uint32_t*)hi)[2 * i]     = h0;
    ((uint32_t*)hi)[2 * i + 1] = h1;
    ((uint32_t*)lo)[2 * i]     = l0;
    ((uint32_t*)lo)[2 * i + 1] = l1;
}

__global__ void k_prep(const float* __restrict__ x, const float* __restrict__ W1,
                       const int* __restrict__ pos)
{
    int b = blockIdx.x;
    if (b < XSPLIT_BLKS) {
        split_chunk(x, g_xhi, g_xlo, b * 256 + threadIdx.x);
    } else if (b < XSPLIT_BLKS + W1SPLIT_BLKS) {
        split_chunk(W1, g_w1hi, g_w1lo, (b - XSPLIT_BLKS) * 256 + threadIdx.x);
    } else {
        int i = (b - XSPLIT_BLKS - W1SPLIT_BLKS) * 256 + threadIdx.x;
        int m = i >> 5, k = i & 31;
        float invf = 1.0f / powf(10000.0f, (2.0f * (float)k) / 64.0f);
        float ang = (float)pos[m] * invf;
        float sn, cs;
        sincosf(ang, &sn, &cs);
        g_cos[i] = cs; g_sin[i] = sn;
    }
}

__global__ void k_split(const float* __restrict__ in, __nv_bfloat16* __restrict__ hi,
                        __nv_bfloat16* __restrict__ lo, int n4)
{
    int i = blockIdx.x * blockDim.x + threadIdx.x;
    if (i >= n4) return;
    split_chunk(in, hi, lo, i);
}

// ---------------------------------------------------------------------------
// Projection GEMM: C[M,N] = A[M,K] @ B[N,K]^T, bf16 3-product split.
// CTA 128x128, BK=32, 3-stage cp.async, single sync/iter, 2 CTAs/SM. (R8)
// ---------------------------------------------------------------------------
#define GARR   8192                         // 128 rows x 64B
#define GSTAGE (4 * GARR)                   // 32KB
#define GEMM_SMEM (3 * GSTAGE)              // 98304 B

template<int EPI>
__global__ __launch_bounds__(256, 2)
void mma_gemm(const __nv_bfloat16* __restrict__ Ahi, const __nv_bfloat16* __restrict__ Alo,
              const __nv_bfloat16* __restrict__ Bhi, const __nv_bfloat16* __restrict__ Blo,
              float* __restrict__ Cf, __nv_bfloat16* __restrict__ Chi,
              __nv_bfloat16* __restrict__ Clo, int M, int N, int K)
{
    extern __shared__ __nv_bfloat16 dsm[];
    const uint32_t sb = smem_u32(dsm);
    const int tid = threadIdx.x, lane = tid & 31, wid = tid >> 5;
    const int m0 = blockIdx.y * 128, n0 = blockIdx.x * 128;
    const int wm = (wid & 1) * 64, wn = (wid >> 1) * 32;

    const int arow = lane & 15,                    acol = (lane & 16) ? 1 : 0;
    const int brow = (lane & 7) + ((lane & 16) ? 8 : 0), bcol = (lane & 8) ? 1 : 0;

    float acc[4][4][4];
#pragma unroll
    for (int a = 0; a < 4; a++)
#pragma unroll
        for (int b = 0; b < 4; b++)
#pragma unroll
            for (int c = 0; c < 4; c++) acc[a][b][c] = 0.f;

    const int nk = K >> 5;

    auto load_stage = [&](int kc, int s) {
        const uint32_t base = sb + (uint32_t)s * GSTAGE;
#pragma unroll
        for (int u = 0; u < 2; u++) {
            int id = tid + u * 256;
            int r = id >> 2, c = id & 3;
            uint32_t so = swz64(r, c);
            size_t ga = (size_t)(m0 + r) * K + kc + c * 8;
            size_t gb = (size_t)(n0 + r) * K + kc + c * 8;
            CP16(base +            so, Ahi + ga);
            CP16(base +     GARR + so, Alo + ga);
            CP16(base + 2 * GARR + so, Bhi + gb);
            CP16(base + 3 * GARR + so, Blo + gb);
        }
        CP_COMMIT();
    };

    load_stage(0, 0);
    load_stage(32, 1);

    for (int kc = 0; kc < nk; kc++) {
        const int cur = kc % 3;
        if (kc == nk - 1) { CP_WAIT0(); } else { CP_WAIT1(); }
        __syncthreads();
        if (kc + 2 < nk) load_stage((kc + 2) << 5, (kc + 2) % 3);

        const uint32_t ab = sb + (uint32_t)cur * GSTAGE;
        const uint32_t bb = ab + 2 * GARR;
#pragma unroll
        for (int ks = 0; ks < 2; ks++) {
            uint32_t ah[4][4], al[4][4];
#pragma unroll
            for (int mf = 0; mf < 4; mf++) {
                uint32_t off = swz64(wm + mf * 16 + arow, ks * 2 + acol);
                ldsm_x4(ah[mf], ab + off);
                ldsm_x4(al[mf], ab + GARR + off);
            }
#pragma unroll
            for (int np = 0; np < 2; np++) {
                uint32_t bh[4], bl[4];
                uint32_t off = swz64(wn + np * 16 + brow, ks * 2 + bcol);
                ldsm_x4(bh, bb + off);
                ldsm_x4(bl, bb + GARR + off);
#pragma unroll
                for (int sel = 0; sel < 2; sel++) {
                    const int nf = np * 2 + sel;
                    uint32_t bh0 = bh[sel * 2], bh1 = bh[sel * 2 + 1];
                    uint32_t bl0 = bl[sel * 2], bl1 = bl[sel * 2 + 1];
#pragma unroll
                    for (int mf = 0; mf < 4; mf++) {
                        mma_bf16(acc[mf][nf], ah[mf], bh0, bh1);
                        mma_bf16(acc[mf][nf], ah[mf], bl0, bl1);
                        mma_bf16(acc[mf][nf], al[mf], bh0, bh1);
                    }
                }
            }
        }
    }

    // epilogue
#pragma unroll
    for (int mf = 0; mf < 4; mf++) {
#pragma unroll
        for (int hf = 0; hf < 2; hf++) {
            const int row = m0 + wm + mf * 16 + (lane >> 2) + hf * 8;
#pragma unroll
            for (int nf = 0; nf < 4; nf++) {
                const int col = n0 + wn + nf * 8 + (lane & 3) * 2;
                float v0 = acc[mf][nf][hf * 2], v1 = acc[mf][nf][hf * 2 + 1];
                if (EPI == 1) {
                    if (col < 2 * DMODEL) {
                        int kidx = (col & 63) >> 1;
                        float cs = g_cos[row * 32 + kidx];
                        float sn = g_sin[row * 32 + kidx];
                        float e = v0, o = v1;
                        v0 = e * cs - o * sn;
                        v1 = o * cs + e * sn;
                        if (col < DMODEL) { v0 *= QSCALE; v1 *= QSCALE; }
                    }
                    uint32_t h, l;
                    split2(v0, v1, h, l);
                    *(uint32_t*)(Chi + (size_t)row * N + col) = h;
                    *(uint32_t*)(Clo + (size_t)row * N + col) = l;
                } else {
                    *(float2*)(Cf + (size_t)row * N + col) = make_float2(v0, v1);
                }
            }
        }
    }
}

// ---------------------------------------------------------------------------
// Causal flash attention (R13 shape): Q-tile 128, K-tile 128 (two 64-col
// passes), 8 warps, single-sync double buffer, no-max exp2 softmax,
// DEFERRED lr reduction (shfl only once, in the epilogue).
// ---------------------------------------------------------------------------
#define ATT_QARR 16384                       // 128 rows x 128B
#define ATT_KARR 16384                       // 128 rows x 128B
#define ATT_SMEM (2 * ATT_QARR + 2 * 4 * ATT_KARR)   // 163840 B

__global__ __launch_bounds__(256)
void attn_mma()
{
    extern __shared__ __nv_bfloat16 sm[];
    const uint32_t sb  = smem_u32(sm);
    const uint32_t kvb = sb + 2 * ATT_QARR;

    const int h   = blockIdx.y;
    const int qt  = gridDim.x - 1 - blockIdx.x;    // big tiles first
    const int tid = threadIdx.x;
    const int lane = tid & 31, w = tid >> 5;

    const int arow = lane & 15,                    acol = (lane & 16) ? 1 : 0;
    const int brow = (lane & 7) + ((lane & 16) ? 8 : 0), bcol = (lane & 8) ? 1 : 0;

    // async Q load (joins K/V stage-0 commit group)
    const size_t qbase = (size_t)(qt * 128) * QKVDIM + h * HSIZE;
#pragma unroll
    for (int u = 0; u < 4; u++) {
        int id = tid + u * 256;
        int r = id >> 3, c = id & 7;
        uint32_t so = swz128(r, c);
        size_t g = qbase + (size_t)r * QKVDIM + c * 8;
        CP16(sb + so,            g_qkvhi + g);
        CP16(sb + ATT_QARR + so, g_qkvlo + g);
    }

    auto load_kv = [&](int kt, int s) {
        const size_t kb = (size_t)(kt * 128) * QKVDIM + DMODEL + h * HSIZE;
        const size_t vb = kb + DMODEL;
        const uint32_t base = kvb + (uint32_t)(s * 4) * ATT_KARR;
#pragma unroll
        for (int u = 0; u < 4; u++) {
            int id = tid + u * 256;
            int r = id >> 3, c = id & 7;
            uint32_t so = swz128(r, c);
            size_t gk = kb + (size_t)r * QKVDIM + c * 8;
            size_t gv = vb + (size_t)r * QKVDIM + c * 8;
            CP16(base +                so, g_qkvhi + gk);
            CP16(base +     ATT_KARR + so, g_qkvlo + gk);
            CP16(base + 2 * ATT_KARR + so, g_qkvhi + gv);
            CP16(base + 3 * ATT_KARR + so, g_qkvlo + gv);
        }
        CP_COMMIT();
    };

    load_kv(0, 0);

    uint32_t qfh[4][4], qfl[4][4];
    float o[8][4];
#pragma unroll
    for (int i = 0; i < 8; i++)
#pragma unroll
        for (int j = 0; j < 4; j++) o[i][j] = 0.f;
    float lr[2] = { 0.f, 0.f };

    const int wrow = qt * 128 + w * 16;        // warp's first global q row

    for (int kt = 0; kt <= qt; kt++) {
        const int cur = kt & 1;
        CP_WAIT0();
        __syncthreads();
        if (kt < qt) load_kv(kt + 1, cur ^ 1);

        if (kt == 0) {
#pragma unroll
            for (int t = 0; t < 4; t++) {
                uint32_t off = swz128(w * 16 + arow, t * 2 + acol);
                ldsm_x4(qfh[t], sb + off);
                ldsm_x4(qfl[t], sb + ATT_QARR + off);
            }
        }

        const uint32_t kbh = kvb + (uint32_t)(cur * 4) * ATT_KARR;
        const uint32_t kbl = kbh + ATT_KARR;
        const uint32_t vbh = kbh + 2 * ATT_KARR;
        const uint32_t vbl = kbh + 3 * ATT_KARR;

#pragma unroll
        for (int half = 0; half < 2; half++) {
            const int colbase = kt * 128 + half * 64;
            if (colbase > wrow + 15) continue;       // fully masked for this warp
            const int rbase = half * 64;             // k-row offset inside the tile

            float s[8][4];
#pragma unroll
            for (int i = 0; i < 8; i++)
#pragma unroll
                for (int j = 0; j < 4; j++) s[i][j] = 0.f;

            // S = Q' K^T (scale+log2e pre-folded into Q)
#pragma unroll
            for (int t = 0; t < 4; t++) {
#pragma unroll
                for (int np = 0; np < 4; np++) {
                    uint32_t bh[4], bl[4];
                    uint32_t off = swz128(rbase + np * 16 + brow, t * 2 + bcol);
                    ldsm_x4(bh, kbh + off);
                    ldsm_x4(bl, kbl + off);
#pragma unroll
                    for (int sel = 0; sel < 2; sel++) {
                        const int nf = np * 2 + sel;
                        uint32_t b0h = bh[sel * 2], b1h = bh[sel * 2 + 1];
                        uint32_t b0l = bl[sel * 2], b1l = bl[sel * 2 + 1];
                        mma_bf16(s[nf], qfh[t], b0h, b1h);
                        mma_bf16(s[nf], qfh[t], b0l, b1l);
                        mma_bf16(s[nf], qfl[t], b0h, b1h);
                    }
                }
            }

            // causal mask (only if this half crosses the warp's rows)
            if (colbase + 63 > wrow) {
                const int r0 = wrow + (lane >> 2), r1 = r0 + 8;
                const int cb = colbase + (lane & 3) * 2;
#pragma unroll
                for (int nf = 0; nf < 8; nf++) {
                    const int c0 = cb + nf * 8;
                    if (c0     > r0) s[nf][0] = -FLT_MAX;
                    if (c0 + 1 > r0) s[nf][1] = -FLT_MAX;
                    if (c0     > r1) s[nf][2] = -FLT_MAX;
                    if (c0 + 1 > r1) s[nf][3] = -FLT_MAX;
                }
            }

            // NO-MAX softmax (exp2 domain, MUFU ex2): p = 2^s; deferred lr
            // (per-thread partial, reduced once in the epilogue).
#pragma unroll
            for (int hf = 0; hf < 2; hf++) {
                float rs = 0.f;
#pragma unroll
                for (int nf = 0; nf < 8; nf++) {
                    float p0 = ex2(s[nf][hf * 2]);
                    float p1 = ex2(s[nf][hf * 2 + 1]);
                    s[nf][hf * 2]     = p0;
                    s[nf][hf * 2 + 1] = p1;
                    rs += p0 + p1;
                }
                lr[hf] += rs;
            }

            // O += P V (P re-split in-register; V via ldmatrix.trans)
#pragma unroll
            for (int t = 0; t < 4; t++) {
                uint32_t ph[4], pl[4];
                split2(s[2 * t][0],     s[2 * t][1],     ph[0], pl[0]);
                split2(s[2 * t][2],     s[2 * t][3],     ph[1], pl[1]);
                split2(s[2 * t + 1][0], s[2 * t + 1][1], ph[2], pl[2]);
                split2(s[2 * t + 1][2], s[2 * t + 1][3], ph[3], pl[3]);
#pragma unroll
                for (int np = 0; np < 4; np++) {
                    uint32_t vh4[4], vl4[4];
                    uint32_t off = swz128(rbase + t * 16 + arow, np * 2 + acol);
                    ldsm_x4_t(vh4, vbh + off);
                    ldsm_x4_t(vl4, vbl + off);
#pragma unroll
                    for (int sel = 0; sel < 2; sel++) {
                        const int df = np * 2 + sel;
                        uint32_t v0h = vh4[sel * 2], v1h = vh4[sel * 2 + 1];
                        uint32_t v0l = vl4[sel * 2], v1l = vl4[sel * 2 + 1];
                        mma_bf16(o[df], ph, v0h, v1h);
                        mma_bf16(o[df], ph, v0l, v1l);
                        mma_bf16(o[df], pl, v0h, v1h);
                    }
                }
            }
        }
    }

    // epilogue: one-time lr reduction, normalize, split, store
#pragma unroll
    for (int hf = 0; hf < 2; hf++) {
        float t = lr[hf];
        t += __shfl_xor_sync(0xffffffffu, t, 1);
        t += __shfl_xor_sync(0xffffffffu, t, 2);
        lr[hf] = t;
    }
#pragma unroll
    for (int hf = 0; hf < 2; hf++) {
        const float inv = 1.0f / lr[hf];
        const int row = wrow + (lane >> 2) + hf * 8;
#pragma unroll
        for (int df = 0; df < 8; df++) {
            const int col = h * 64 + df * 8 + (lane & 3) * 2;
            float v0 = o[df][hf * 2] * inv, v1 = o[df][hf * 2 + 1] * inv;
            uint32_t hh, ll;
            split2(v0, v1, hh, ll);
            *(uint32_t*)(g_ahi + (size_t)row * DMODEL + col) = hh;
            *(uint32_t*)(g_alo + (size_t)row * DMODEL + col) = ll;
        }
    }
}

// ---------------------------------------------------------------------------
extern "C" void kernel_launch(void* const* d_in, const int* in_sizes, int n_in,
                              void* d_out, int out_size)
{
    const float* x    = (const float*)d_in[0];
    const int*   pos  = (const int*)  d_in[1];
    const float* Wqkv = (const float*)d_in[2];
    const float* Wo   = (const float*)d_in[3];
    float*       out  = (float*)d_out;

    __nv_bfloat16 *xhi, *xlo, *w1hi, *w1lo, *w2hi, *w2lo, *qkvhi, *qkvlo, *ahi, *alo;
    cudaGetSymbolAddress((void**)&xhi,   g_xhi);
    cudaGetSymbolAddress((void**)&xlo,   g_xlo);
    cudaGetSymbolAddress((void**)&w1hi,  g_w1hi);
    cudaGetSymbolAddress((void**)&w1lo,  g_w1lo);
    cudaGetSymbolAddress((void**)&w2hi,  g_w2hi);
    cudaGetSymbolAddress((void**)&w2lo,  g_w2lo);
    cudaGetSymbolAddress((void**)&qkvhi, g_qkvhi);
    cudaGetSymbolAddress((void**)&qkvlo, g_qkvlo);
    cudaGetSymbolAddress((void**)&ahi,   g_ahi);
    cudaGetSymbolAddress((void**)&alo,   g_alo);

    cudaFuncSetAttribute(mma_gemm<1>,
                         cudaFuncAttributeMaxDynamicSharedMemorySize, GEMM_SMEM);
    cudaFuncSetAttribute(mma_gemm<0>,
                         cudaFuncAttributeMaxDynamicSharedMemorySize, GEMM_SMEM);
    cudaFuncSetAttribute(attn_mma,
                         cudaFuncAttributeMaxDynamicSharedMemorySize, ATT_SMEM);

    // 1) fused prep: x-split + W1-split + RoPE tables
    k_prep<<<PREP_BLKS, 256>>>(x, Wqkv, pos);

    // 2) QKV projection + RoPE + q-prescale + split store
    mma_gemm<1><<<dim3(QKVDIM / 128, SEQ / 128), 256, GEMM_SMEM>>>(
        xhi, xlo, w1hi, w1lo, nullptr, qkvhi, qkvlo, SEQ, QKVDIM, DMODEL);

    // 3) W_o split (independent)
    k_split<<<(DMODEL * DMODEL / 4 + 255) / 256, 256>>>(Wo, w2hi, w2lo, DMODEL * DMODEL / 4);

    // 4) Causal flash attention  <-- ncu capture lands here
    attn_mma<<<dim3(SEQ / 128, NHEADS), 256, ATT_SMEM>>>();

    // 5) Output projection -> fp32 out
    mma_gemm<0><<<dim3(DMODEL / 128, SEQ / 128), 256, GEMM_SMEM>>>(
        ahi, alo, w2hi, w2lo, out, nullptr, nullptr, SEQ, DMODEL, DMODEL);
}